// round 6
// baseline (speedup 1.0000x reference)
#include <cuda_runtime.h>
#include <cuda_fp16.h>
#include <cstdint>

#define OUT_DIM 8192
#define IN_DIM  8192
#define NGRP    64                 /* scale groups per output row (GS=128) */
#define KSTEPS  512                /* IN_DIM / 16 */
#define KSPLIT  4                  /* K split across the 4 warps of a CTA */
#define KS_W    (KSTEPS / KSPLIT)  /* 128 ksteps per warp */
#define DEPTH_S 8                  /* cp.async smem ring stages (A) */
#define DEPTH_B 8                  /* B register prefetch depth (L2-resident) */

// x pre-packed per (kstep, lane): 2 uint4 = fragments for all 4 ntiles.
// k is PERMUTED inside each 16-wide kstep: fragment positions
// (2tig, 2tig+1, 2tig+8, 2tig+9) hold physical k (4tig..4tig+3).
// A uses the same permutation, so the MMA result is unchanged.
__device__ uint4 g_xfrag[KSTEPS * 32 * 2];

__global__ void xconv_kernel(const float* __restrict__ x) {
    const int idx  = blockIdx.x * blockDim.x + threadIdx.x;   // 0..16383
    const int lane = idx & 31;
    const int kt   = idx >> 5;
    const int g    = lane >> 2;
    const int tig  = lane & 3;
    const int k0   = kt * 16 + tig * 4;

    unsigned w[8];
    #pragma unroll
    for (int nt = 0; nt < 4; nt++) {
        const int n = nt * 8 + g;
        const float4 a = *reinterpret_cast<const float4*>(x + n * IN_DIM + k0);
        __half2 lo = __floats2half2_rn(a.x, a.y);
        __half2 hi = __floats2half2_rn(a.z, a.w);
        w[nt * 2]     = *reinterpret_cast<unsigned*>(&lo);
        w[nt * 2 + 1] = *reinterpret_cast<unsigned*>(&hi);
    }
    g_xfrag[idx * 2]     = make_uint4(w[0], w[1], w[2], w[3]);
    g_xfrag[idx * 2 + 1] = make_uint4(w[4], w[5], w[6], w[7]);
}

// t in {-1,0,1}: low 16 bits of (t<<14) are exactly fp16(2t). Pack a pair, then
// scale by half2(s/2): products are +-fp16(s), exact (x2 only shifts the exponent).
__device__ __forceinline__ unsigned cvt_pair(unsigned t0, unsigned t1, unsigned sh2) {
    unsigned u0 = t0 << 14;
    unsigned u1 = t1 << 14;
    unsigned p;
    asm("prmt.b32 %0, %1, %2, 0x5410;" : "=r"(p) : "r"(u0), "r"(u1));
    asm("mul.rn.f16x2 %0, %1, %2;" : "=r"(p) : "r"(p), "r"(sh2));
    return p;
}

__device__ __forceinline__ void mma16816(float c[4], unsigned a0, unsigned a1,
                                         unsigned a2, unsigned a3,
                                         unsigned b0, unsigned b1) {
    asm("mma.sync.aligned.m16n8k16.row.col.f32.f16.f16.f32 "
        "{%0,%1,%2,%3}, {%4,%5,%6,%7}, {%8,%9}, {%0,%1,%2,%3};"
        : "+f"(c[0]), "+f"(c[1]), "+f"(c[2]), "+f"(c[3])
        : "r"(a0), "r"(a1), "r"(a2), "r"(a3), "r"(b0), "r"(b1));
}

__device__ __forceinline__ unsigned smem_u32(const void* p) {
    unsigned a;
    asm("{ .reg .u64 t; cvta.to.shared.u64 t, %1; cvt.u32.u64 %0, t; }"
        : "=r"(a) : "l"(p));
    return a;
}
#define CP_ASYNC16(dst, src) \
    asm volatile("cp.async.cg.shared.global [%0], [%1], 16;" \
                 :: "r"(dst), "l"(src) : "memory")
#define CP_COMMIT() asm volatile("cp.async.commit_group;" ::: "memory")
#define CP_WAIT(n)  asm volatile("cp.async.wait_group %0;" :: "n"(n) : "memory")

__global__ __launch_bounds__(128, 4)
void tmma_kernel(const int* __restrict__ tern,
                 const float* __restrict__ scales,
                 float* __restrict__ out)
{
    // Per-warp-private A ring: [warp][stage][64 int4] = 1KB/stage, 32KB total.
    __shared__ int4  ringA[KSPLIT][DEPTH_S][64];
    __shared__ float red[KSPLIT][32][16];

    const int lane = threadIdx.x & 31;
    const int kg   = threadIdx.x >> 5;       // warp = K quarter (0..3)
    const int g    = lane >> 2;
    const int tig  = lane & 3;
    const int o_tile = blockIdx.x * 16;      // CTA: 16 o-rows x all 32 t x full K
    const int row0 = o_tile + g;
    const int row1 = row0 + 8;
    const int kbase = kg * KS_W;

    const int4* pA0 = reinterpret_cast<const int4*>(tern + (long)row0 * IN_DIM + kbase * 16 + tig * 4);
    const int4* pA1 = reinterpret_cast<const int4*>(tern + (long)row1 * IN_DIM + kbase * 16 + tig * 4);
    const uint4* pB = g_xfrag + (long)(kbase * 32 + lane) * 2;

    // Lane-local smem slots: what a lane cp.async's is exactly what it LDSes.
    const unsigned s_a0 = smem_u32(&ringA[kg][0][lane]);
    const unsigned s_a1 = smem_u32(&ringA[kg][0][32 + lane]);

    float acc[4][4];
    #pragma unroll
    for (int n = 0; n < 4; n++)
        #pragma unroll
        for (int i = 0; i < 4; i++) acc[n][i] = 0.f;

    uint4 bbuf[DEPTH_B][2];

    // Prologue: fill the A ring (8 groups outstanding) and the B register pipe.
    #pragma unroll
    for (int d = 0; d < DEPTH_S; d++) {
        CP_ASYNC16(s_a0 + d * 1024, pA0 + d * 4);
        CP_ASYNC16(s_a1 + d * 1024, pA1 + d * 4);
        CP_COMMIT();
    }
    #pragma unroll
    for (int d = 0; d < DEPTH_B; d++) {
        bbuf[d][0] = pB[d * 64];
        bbuf[d][1] = pB[d * 64 + 1];
    }

    unsigned sh0 = 0, sh1 = 0;

    #pragma unroll 8
    for (int ks = 0; ks < KS_W; ks++) {
        if ((ks & 7) == 0) {                 // new scale group (GS=128 = 8 ksteps)
            const int grp = (kbase + ks) >> 3;
            const float s0 = __ldg(scales + row0 * NGRP + grp) * 0.5f;
            const float s1 = __ldg(scales + row1 * NGRP + grp) * 0.5f;
            const __half2 p0 = __half2half2(__float2half_rn(s0));
            const __half2 p1 = __half2half2(__float2half_rn(s1));
            sh0 = *reinterpret_cast<const unsigned*>(&p0);
            sh1 = *reinterpret_cast<const unsigned*>(&p1);
        }

        const int st = ks & (DEPTH_S - 1);
        const int ib = ks & (DEPTH_B - 1);

        // Oldest A group complete once <= DEPTH_S-1 remain (dummy commits keep
        // the FIFO arithmetic uniform through the tail).
        CP_WAIT(DEPTH_S - 1);

        const int4 va0 = ringA[kg][st][lane];        // LDS.128, lane-local
        const int4 va1 = ringA[kg][st][32 + lane];
        const uint4 vb0 = bbuf[ib][0];
        const uint4 vb1 = bbuf[ib][1];

        // Refill pipelines.
        const int ka = ks + DEPTH_S;
        if (ka < KS_W) {
            CP_ASYNC16(s_a0 + st * 1024, pA0 + ka * 4);
            CP_ASYNC16(s_a1 + st * 1024, pA1 + ka * 4);
        }
        CP_COMMIT();                                  // unconditional (tail dummies)
        const int kb = ks + DEPTH_B;
        if (kb < KS_W) {
            bbuf[ib][0] = pB[kb * 64];
            bbuf[ib][1] = pB[kb * 64 + 1];
        }

        const unsigned a0 = cvt_pair((unsigned)va0.x, (unsigned)va0.y, sh0);
        const unsigned a2 = cvt_pair((unsigned)va0.z, (unsigned)va0.w, sh0);
        const unsigned a1 = cvt_pair((unsigned)va1.x, (unsigned)va1.y, sh1);
        const unsigned a3 = cvt_pair((unsigned)va1.z, (unsigned)va1.w, sh1);

        mma16816(acc[0], a0, a1, a2, a3, vb0.x, vb0.y);
        mma16816(acc[1], a0, a1, a2, a3, vb0.z, vb0.w);
        mma16816(acc[2], a0, a1, a2, a3, vb1.x, vb1.y);
        mma16816(acc[3], a0, a1, a2, a3, vb1.z, vb1.w);
    }

    // Deterministic cross-warp K reduction through smem (fixed summation order).
    #pragma unroll
    for (int nt = 0; nt < 4; nt++)
        #pragma unroll
        for (int i = 0; i < 4; i++)
            red[kg][lane][nt * 4 + i] = acc[nt][i];
    __syncthreads();

    if (kg == 0) {
        #pragma unroll
        for (int nt = 0; nt < 4; nt++) {
            const int t = nt * 8 + tig * 2;
            #pragma unroll
            for (int i = 0; i < 4; i++) {
                const int idx = nt * 4 + i;
                float s = red[0][lane][idx];
                #pragma unroll
                for (int w = 1; w < KSPLIT; w++) s += red[w][lane][idx];
                const int row = (i < 2) ? row0 : row1;
                const int tt  = t + (i & 1);
                out[(long)tt * OUT_DIM + row] = s;
            }
        }
    }
}

extern "C" void kernel_launch(void* const* d_in, const int* in_sizes, int n_in,
                              void* d_out, int out_size) {
    const float* x      = (const float*)d_in[0];
    const int*   tern   = (const int*)d_in[1];
    const float* scales = (const float*)d_in[2];
    float*       out    = (float*)d_out;

    xconv_kernel<<<64, 256>>>(x);
    tmma_kernel<<<OUT_DIM / 16, 128>>>(tern, scales, out);
}

// round 7
// speedup vs baseline: 1.0037x; 1.0037x over previous
#include <cuda_runtime.h>
#include <cuda_fp16.h>
#include <cstdint>

#define OUT_DIM 8192
#define IN_DIM  8192
#define NGRP    64                 /* scale groups per output row (GS=128) */
#define KSTEPS  512                /* IN_DIM / 16 */
#define KSPLIT  8                  /* K split across the 8 warps of a CTA */
#define KS_W    (KSTEPS / KSPLIT)  /* 64 ksteps per warp */
#define O_CTA   32                 /* o-rows per CTA (per warp: all 32) */
#define DEPTH_S 6                  /* cp.async smem ring stages (A) */
#define DEPTH_B 4                  /* B register prefetch depth (L2-resident) */
#define STAGE_I4 128               /* int4 per ring stage per warp (4 streams x 32 lanes) */
#define RING_BYTES (KSPLIT * DEPTH_S * 2048)   /* 96 KB */

// x pre-packed per (kstep, lane): 2 uint4 = fragments for all 4 ntiles.
// k is PERMUTED inside each 16-wide kstep: fragment positions
// (2tig, 2tig+1, 2tig+8, 2tig+9) hold physical k (4tig..4tig+3).
// A uses the same permutation, so the MMA result is unchanged.
__device__ uint4 g_xfrag[KSTEPS * 32 * 2];

__global__ void xconv_kernel(const float* __restrict__ x) {
    const int idx  = blockIdx.x * blockDim.x + threadIdx.x;   // 0..16383
    const int lane = idx & 31;
    const int kt   = idx >> 5;
    const int g    = lane >> 2;
    const int tig  = lane & 3;
    const int k0   = kt * 16 + tig * 4;

    unsigned w[8];
    #pragma unroll
    for (int nt = 0; nt < 4; nt++) {
        const int n = nt * 8 + g;
        const float4 a = *reinterpret_cast<const float4*>(x + n * IN_DIM + k0);
        __half2 lo = __floats2half2_rn(a.x, a.y);
        __half2 hi = __floats2half2_rn(a.z, a.w);
        w[nt * 2]     = *reinterpret_cast<unsigned*>(&lo);
        w[nt * 2 + 1] = *reinterpret_cast<unsigned*>(&hi);
    }
    g_xfrag[idx * 2]     = make_uint4(w[0], w[1], w[2], w[3]);
    g_xfrag[idx * 2 + 1] = make_uint4(w[4], w[5], w[6], w[7]);
}

// t in {-1,0,1}: low 16 bits of (t<<14) are exactly fp16(2t). Pack a pair, then
// scale by half2(s/2): products are +-fp16(s), exact (x2 only shifts the exponent).
__device__ __forceinline__ unsigned cvt_pair(unsigned t0, unsigned t1, unsigned sh2) {
    unsigned u0 = t0 << 14;
    unsigned u1 = t1 << 14;
    unsigned p;
    asm("prmt.b32 %0, %1, %2, 0x5410;" : "=r"(p) : "r"(u0), "r"(u1));
    asm("mul.rn.f16x2 %0, %1, %2;" : "=r"(p) : "r"(p), "r"(sh2));
    return p;
}

__device__ __forceinline__ void mma16816(float c[4], unsigned a0, unsigned a1,
                                         unsigned a2, unsigned a3,
                                         unsigned b0, unsigned b1) {
    asm("mma.sync.aligned.m16n8k16.row.col.f32.f16.f16.f32 "
        "{%0,%1,%2,%3}, {%4,%5,%6,%7}, {%8,%9}, {%0,%1,%2,%3};"
        : "+f"(c[0]), "+f"(c[1]), "+f"(c[2]), "+f"(c[3])
        : "r"(a0), "r"(a1), "r"(a2), "r"(a3), "r"(b0), "r"(b1));
}

__device__ __forceinline__ unsigned smem_u32(const void* p) {
    unsigned a;
    asm("{ .reg .u64 t; cvta.to.shared.u64 t, %1; cvt.u32.u64 %0, t; }"
        : "=r"(a) : "l"(p));
    return a;
}
#define CP_ASYNC16(dst, src) \
    asm volatile("cp.async.cg.shared.global [%0], [%1], 16;" \
                 :: "r"(dst), "l"(src) : "memory")
#define CP_COMMIT() asm volatile("cp.async.commit_group;" ::: "memory")
#define CP_WAIT(n)  asm volatile("cp.async.wait_group %0;" :: "n"(n) : "memory")

extern "C" __global__ void __launch_bounds__(256, 2)
tmma_kernel(const int* __restrict__ tern,
            const float* __restrict__ scales,
            float* __restrict__ out)
{
    extern __shared__ char sm[];   // [KSPLIT][DEPTH_S][4 streams][32 lanes] int4 ring

    const int lane = threadIdx.x & 31;
    const int kg   = threadIdx.x >> 5;       // warp = K eighth (0..7)
    const int g    = lane >> 2;
    const int tig  = lane & 3;
    const int o_tile = blockIdx.x * O_CTA;   // CTA: 32 o-rows x all 32 t x full K
    const int kbase = kg * KS_W;

    // 4 A row-streams: rows o_tile + s*8 + g  (tiles: (s0,s1) and (s2,s3)).
    const int4* pA[4];
    #pragma unroll
    for (int s = 0; s < 4; s++)
        pA[s] = reinterpret_cast<const int4*>(
            tern + (long)(o_tile + s * 8 + g) * IN_DIM + kbase * 16 + tig * 4);
    const uint4* pB = g_xfrag + (long)(kbase * 32 + lane) * 2;

    // Lane-local smem slots (cp.async dst == this lane's LDS src).
    const unsigned ring0 = smem_u32(sm) + kg * (DEPTH_S * 2048) + lane * 16;
    const int4* ringp = reinterpret_cast<const int4*>(sm) + kg * (DEPTH_S * STAGE_I4) + lane;

    float acc[2][4][4];                      // [m-tile][ntile][frag]
    #pragma unroll
    for (int m = 0; m < 2; m++)
        #pragma unroll
        for (int n = 0; n < 4; n++)
            #pragma unroll
            for (int i = 0; i < 4; i++) acc[m][n][i] = 0.f;

    uint4 bbuf[DEPTH_B][2];

    // Prologue: fill A ring and B register pipe.
    #pragma unroll
    for (int d = 0; d < DEPTH_S; d++) {
        #pragma unroll
        for (int s = 0; s < 4; s++)
            CP_ASYNC16(ring0 + d * 2048 + s * 512, pA[s] + d * 4);
        CP_COMMIT();
    }
    #pragma unroll
    for (int d = 0; d < DEPTH_B; d++) {
        bbuf[d][0] = pB[d * 64];
        bbuf[d][1] = pB[d * 64 + 1];
    }

    unsigned sh[4] = {0, 0, 0, 0};

    #pragma unroll 4
    for (int ks = 0; ks < KS_W; ks++) {
        if ((ks & 7) == 0) {                 // new scale group (GS=128 = 8 ksteps)
            const int grp = (kbase + ks) >> 3;
            #pragma unroll
            for (int s = 0; s < 4; s++) {
                const float sc = __ldg(scales + (o_tile + s * 8 + g) * NGRP + grp) * 0.5f;
                const __half2 p = __half2half2(__float2half_rn(sc));
                sh[s] = *reinterpret_cast<const unsigned*>(&p);
            }
        }

        const int st = ks % DEPTH_S;
        const int ib = ks & (DEPTH_B - 1);

        CP_WAIT(DEPTH_S - 1);                // oldest stage resident

        int4 va[4];
        #pragma unroll
        for (int s = 0; s < 4; s++)
            va[s] = ringp[st * STAGE_I4 + s * 32];      // LDS.128, lane-local
        const uint4 vb0 = bbuf[ib][0];
        const uint4 vb1 = bbuf[ib][1];

        // Refill (dummy commits keep FIFO arithmetic uniform at the tail).
        const int ka = ks + DEPTH_S;
        if (ka < KS_W) {
            #pragma unroll
            for (int s = 0; s < 4; s++)
                CP_ASYNC16(ring0 + st * 2048 + s * 512, pA[s] + ka * 4);
        }
        CP_COMMIT();
        const int kb = ks + DEPTH_B;
        if (kb < KS_W) {
            bbuf[ib][0] = pB[kb * 64];
            bbuf[ib][1] = pB[kb * 64 + 1];
        }

        #pragma unroll
        for (int m = 0; m < 2; m++) {
            const int4 v0 = va[m * 2];
            const int4 v1 = va[m * 2 + 1];
            const unsigned a0 = cvt_pair((unsigned)v0.x, (unsigned)v0.y, sh[m * 2]);
            const unsigned a2 = cvt_pair((unsigned)v0.z, (unsigned)v0.w, sh[m * 2]);
            const unsigned a1 = cvt_pair((unsigned)v1.x, (unsigned)v1.y, sh[m * 2 + 1]);
            const unsigned a3 = cvt_pair((unsigned)v1.z, (unsigned)v1.w, sh[m * 2 + 1]);
            mma16816(acc[m][0], a0, a1, a2, a3, vb0.x, vb0.y);
            mma16816(acc[m][1], a0, a1, a2, a3, vb0.z, vb0.w);
            mma16816(acc[m][2], a0, a1, a2, a3, vb1.x, vb1.y);
            mma16816(acc[m][3], a0, a1, a2, a3, vb1.z, vb1.w);
        }
    }

    // Deterministic cross-warp K reduction; ring smem reused as the buffer.
    CP_WAIT(0);
    __syncthreads();
    float* red = reinterpret_cast<float*>(sm);          // [KSPLIT][32][32]
    #pragma unroll
    for (int m = 0; m < 2; m++)
        #pragma unroll
        for (int nt = 0; nt < 4; nt++)
            #pragma unroll
            for (int i = 0; i < 4; i++)
                red[(kg * 32 + lane) * 32 + m * 16 + nt * 4 + i] = acc[m][nt][i];
    __syncthreads();

    // Warp kg sums j in [kg*4, kg*4+4) over all 8 warps in fixed order.
    #pragma unroll
    for (int jj = 0; jj < 4; jj++) {
        const int j = kg * 4 + jj;
        float s = red[lane * 32 + j];                   // w = 0
        #pragma unroll
        for (int w = 1; w < KSPLIT; w++)
            s += red[(w * 32 + lane) * 32 + j];
        const int m  = j >> 4;
        const int nt = (j >> 2) & 3;
        const int i  = j & 3;
        const int row = o_tile + m * 16 + ((i & 2) ? 8 : 0) + g;
        const int t   = nt * 8 + tig * 2 + (i & 1);
        out[(long)t * OUT_DIM + row] = s;
    }
}

extern "C" void kernel_launch(void* const* d_in, const int* in_sizes, int n_in,
                              void* d_out, int out_size) {
    const float* x      = (const float*)d_in[0];
    const int*   tern   = (const int*)d_in[1];
    const float* scales = (const float*)d_in[2];
    float*       out    = (float*)d_out;

    cudaFuncSetAttribute(tmma_kernel,
                         cudaFuncAttributeMaxDynamicSharedMemorySize, RING_BYTES);
    xconv_kernel<<<64, 256>>>(x);
    tmma_kernel<<<OUT_DIM / O_CTA, 256, RING_BYTES>>>(tern, scales, out);
}